// round 8
// baseline (speedup 1.0000x reference)
#include <cuda_runtime.h>
#include <cstdint>

#define CIN   128
#define KOUT  256
#define HH    56
#define WW    56
#define NIMG  32
#define HWSZ  (HH*WW)            // 3136
#define XROWS 58                 // rows -1..56 stored at index ih+1
#define XROWF 64                 // permuted 64-float row, pixel w = cw-4
#define XPLANE (XROWS*XROWF)     // 3712

#define TILE_M   64
#define ROWS_CTA 4
#define NGROUP   (HH/ROWS_CTA)   // 14
#define NCHUNK   16
#define CPC      8

// smem per stage (floats):
//  A: [tap(9)][mtile(4)][lane(32)][4] = 4608
//  B: [c(8)] x (6 rows x 64 + 8 pad = 392) = 3136
#define A_FLOATS 4608
#define B_FLOATS 3136
#define STAGE_FLOATS (A_FLOATS + B_FLOATS)   // 7744
#define STAGE_BYTES  (STAGE_FLOATS*4)        // 30976
#define STAGES 3
#define SMEM_BYTES   (STAGES*STAGE_BYTES)    // 92928

__device__ __align__(64) float XT[(size_t)NIMG*CIN*XPLANE];
__device__ float WT2[(size_t)1152*KOUT];     // [chunk][tap][mtile16][lane][4]

__device__ __forceinline__ float rna_tf32(float v) {
    uint32_t u;
    asm("cvt.rna.tf32.f32 %0, %1;" : "=r"(u) : "f"(v));
    return __uint_as_float(u);
}
__device__ __forceinline__ void mma_tf32(float* d, const uint32_t* a, const uint32_t* b) {
    asm volatile(
        "mma.sync.aligned.m16n8k8.row.col.f32.tf32.tf32.f32 "
        "{%0,%1,%2,%3}, {%4,%5,%6,%7}, {%8,%9}, {%0,%1,%2,%3};"
        : "+f"(d[0]), "+f"(d[1]), "+f"(d[2]), "+f"(d[3])
        : "r"(a[0]), "r"(a[1]), "r"(a[2]), "r"(a[3]), "r"(b[0]), "r"(b[1]));
}
__device__ __forceinline__ void cp16(uint32_t dst, const void* src) {
    asm volatile("cp.async.cg.shared.global [%0], [%1], 16;" :: "r"(dst), "l"(src));
}
__device__ __forceinline__ void lds128(uint32_t* r, uint32_t addr) {
    asm volatile("ld.shared.v4.b32 {%0,%1,%2,%3}, [%4];"
                 : "=r"(r[0]), "=r"(r[1]), "=r"(r[2]), "=r"(r[3]) : "r"(addr));
}

// ---------------- combined transform ----------------
// blocks [0,4096): x planes -> permuted XT.  blocks [4096,5248): weights.
__global__ void transform_all(const float* __restrict__ x, const float* __restrict__ k) {
    const int bid = blockIdx.x;
    const int t = threadIdx.x;
    if (bid < NIMG * CIN) {
        __shared__ float srow[HWSZ];
        const float4* src = reinterpret_cast<const float4*>(x + (size_t)bid * HWSZ);
        float4* dst = reinterpret_cast<float4*>(XT + (size_t)bid * XPLANE);
        #pragma unroll
        for (int q = 0; q < 4; ++q) {
            const int idx = q * 256 + t;
            if (idx < 784) {
                float4 v = src[idx];
                v.x = rna_tf32(v.x); v.y = rna_tf32(v.y);
                v.z = rna_tf32(v.z); v.w = rna_tf32(v.w);
                *reinterpret_cast<float4*>(srow + idx * 4) = v;
            }
        }
        __syncthreads();
        // 928 permuted f4 writes: f4 #k of row rr covers cw = ((k&1)*4+jj)*8 + (k>>1)
        #pragma unroll
        for (int q = 0; q < 4; ++q) {
            const int idx = q * 256 + t;
            if (idx < 928) {
                const int rr = idx >> 4;      // 0..57, ih = rr-1
                const int kk = idx & 15;
                float4 v = make_float4(0.f, 0.f, 0.f, 0.f);
                if (rr > 0 && rr < 57) {
                    const int h = rr - 1;
                    const int blk = kk >> 1;
                    const int jb  = (kk & 1) * 4;
                    float* p = &v.x;
                    #pragma unroll
                    for (int jj = 0; jj < 4; ++jj) {
                        const int w = (jb + jj) * 8 + blk - 4;
                        p[jj] = ((unsigned)w < (unsigned)WW) ? srow[h * WW + w] : 0.0f;
                    }
                }
                dst[idx] = v;
            }
        }
    } else {
        const int idx = (bid - NIMG * CIN) * 256 + t;      // 294912 total
        const int chunk = idx / 18432;
        int r1 = idx - chunk * 18432;
        const int tap = r1 / 2048;  r1 -= tap * 2048;
        const int mt  = r1 >> 7;
        const int ln  = (r1 >> 2) & 31;
        const int j   = r1 & 3;
        const int g   = ln >> 2, t4 = ln & 3;
        const int m   = mt * 16 + g + (j & 1) * 8;
        const int c   = chunk * CPC + t4 + (j >> 1) * 4;
        WT2[idx] = rna_tf32(k[(size_t)(m * CIN + c) * 9 + tap]);
    }
}

// ---------------- main kernel ----------------
__global__ void __launch_bounds__(256, 2)
conv_mma(const float* __restrict__ bias, float* __restrict__ out) {
    extern __shared__ float sm[];
    const int t    = threadIdx.x;
    const int warp = t >> 5;
    const int lane = t & 31;
    const int g    = lane >> 2;
    const int t4   = lane & 3;
    const int wm   = warp >> 2;     // 0..1 : M halves of 32
    const int wn   = warp & 3;      // 0..3 : output row within group
    const int img  = blockIdx.y / NGROUP;
    const int grp  = blockIdx.y - img * NGROUP;
    const int oh0  = grp * ROWS_CTA;
    const int my0  = blockIdx.x * 4;
    const int m0   = blockIdx.x * TILE_M;

    uint32_t sm_u32;
    { uint64_t tmp = __cvta_generic_to_shared(sm); sm_u32 = (uint32_t)tmp; }

    float acc[2][7][4];
    #pragma unroll
    for (int mi = 0; mi < 2; ++mi)
        #pragma unroll
        for (int nj = 0; nj < 7; ++nj)
            #pragma unroll
            for (int q = 0; q < 4; ++q) acc[mi][nj][q] = 0.0f;

    const float* xg_base = XT + ((size_t)img * CIN) * XPLANE + (size_t)oh0 * XROWF;

    auto issue = [&](int chunk, int stage) {
        const uint32_t ab = sm_u32 + stage * STAGE_BYTES;
        const uint32_t bb = ab + A_FLOATS * 4;
        const float* ag = WT2 + (size_t)chunk * 18432;
        #pragma unroll
        for (int q = 0; q < 5; ++q) {
            const int idx = q * 256 + t;
            if (idx < 1152) {
                const int tap  = idx >> 7;
                const int rem  = idx & 127;
                const int tile = rem >> 5;
                const int ln2  = rem & 31;
                cp16(ab + idx * 16,
                     ag + (size_t)tap * 2048 + (size_t)(my0 + tile) * 128 + ln2 * 4);
            }
        }
        // B: 768 f4 = 8c x 6 rows x 16 f4 (verbatim permuted rows)
        #pragma unroll
        for (int q = 0; q < 3; ++q) {
            const int idx = q * 256 + t;
            const int c   = idx / 96;
            const int rem = idx - c * 96;
            const int row = rem >> 4;
            const int f   = rem & 15;
            cp16(bb + (c * 392 + row * 64 + f * 4) * 4,
                 xg_base + (size_t)(chunk * CPC + c) * XPLANE + row * XROWF + f * 4);
        }
    };

    issue(0, 0);
    asm volatile("cp.async.commit_group;" ::: "memory");
    issue(1, 1);
    asm volatile("cp.async.commit_group;" ::: "memory");

    int stage = 0, stage2 = 2;
    for (int chunk = 0; chunk < NCHUNK; ++chunk) {
        asm volatile("cp.async.wait_group 1;" ::: "memory");
        __syncthreads();

        const uint32_t a_base = sm_u32 + stage * STAGE_BYTES + (wm * 2) * 512 + lane * 16;
        const uint32_t b_root = sm_u32 + stage * STAGE_BYTES + (A_FLOATS + t4 * 392) * 4;

        #pragma unroll
        for (int tap = 0; tap < 9; ++tap) {
            const int r = tap / 3;
            const int s = tap - r * 3;
            const int q = g + s + 3;
            const int shift = q >> 3;          // 0 or 1
            const int blk   = q & 7;

            uint32_t a[2][4];
            lds128(a[0], a_base + tap * 2048);
            lds128(a[1], a_base + tap * 2048 + 512);

            const uint32_t b0a = b_root + ((wn + r) * 64 + blk * 8) * 4;
            uint32_t v0[8], v1[8];
            lds128(v0,     b0a);
            lds128(v0 + 4, b0a + 16);
            lds128(v1,     b0a + 6272);        // +4*392 floats
            lds128(v1 + 4, b0a + 6272 + 16);

            #pragma unroll
            for (int nj = 0; nj < 7; ++nj) {
                uint32_t bfr[2];
                bfr[0] = shift ? v0[nj + 1] : v0[nj];
                bfr[1] = shift ? v1[nj + 1] : v1[nj];
                mma_tf32(acc[0][nj], a[0], bfr);
                mma_tf32(acc[1][nj], a[1], bfr);
            }
        }

        if (chunk + 2 < NCHUNK) issue(chunk + 2, stage2);
        asm volatile("cp.async.commit_group;" ::: "memory");

        stage  = (stage  == 2) ? 0 : stage  + 1;
        stage2 = (stage2 == 2) ? 0 : stage2 + 1;
    }

    // ---- epilogue ----
    const float bv = bias[0];
    const int orow = oh0 + wn;
    #pragma unroll
    for (int mi = 0; mi < 2; ++mi) {
        const int kch = m0 + wm * 32 + mi * 16 + g;
        float* o = out + ((size_t)img * KOUT + kch) * HWSZ + (size_t)orow * WW;
        #pragma unroll
        for (int nj = 0; nj < 7; ++nj) {
            const int ow = nj * 8 + 2 * t4;
            *reinterpret_cast<float2*>(o + ow) =
                make_float2(acc[mi][nj][0] + bv, acc[mi][nj][1] + bv);
            *reinterpret_cast<float2*>(o + 8 * HWSZ + ow) =
                make_float2(acc[mi][nj][2] + bv, acc[mi][nj][3] + bv);
        }
    }
}

// ---------------- host ----------------
extern "C" void kernel_launch(void* const* d_in, const int* in_sizes, int n_in,
                              void* d_out, int out_size) {
    const float* x    = (const float*)d_in[0];
    const float* K    = (const float*)d_in[1];
    const float* bias = (const float*)d_in[2];
    float* out        = (float*)d_out;

    cudaFuncSetAttribute(conv_mma, cudaFuncAttributeMaxDynamicSharedMemorySize, SMEM_BYTES);

    transform_all<<<NIMG * CIN + 1152, 256>>>(x, K);
    dim3 grid(KOUT / TILE_M, NIMG * NGROUP);   // (4, 448)
    conv_mma<<<grid, 256, SMEM_BYTES>>>(bias, out);
}

// round 9
// speedup vs baseline: 2.0667x; 2.0667x over previous
#include <cuda_runtime.h>
#include <cuda_fp16.h>
#include <cstdint>

#define CIN   128
#define KOUT  256
#define HH    56
#define WW    56
#define NIMG  32
#define HWSZ  (HH*WW)            // 3136
#define XPLANE (58*60)           // b32 units per (n,c2) plane; unit=2 fp16 ch
#define NC2   64                 // channel pairs

#define TILE_M   64
#define ROWS_CTA 4
#define NGROUP   (HH/ROWS_CTA)   // 14
#define NCHUNK   8               // chunks of 16 channels (8 c2-pairs)

// smem per stage (b32 units):
//  A: [tap(9)][mtile(4)][lane(32)][4] = 4608 units (18432 B)
//  B: [c2(8)] x (6 rows x 64 + 8 pad = 392) = 3136 units (12544 B)
#define A_UNITS 4608
#define B_UNITS 3136
#define STAGE_UNITS (A_UNITS + B_UNITS)      // 7744
#define STAGE_BYTES (STAGE_UNITS*4)          // 30976
#define STAGES 3
#define SMEM_BYTES (STAGES*STAGE_BYTES)      // 92928

#define GUARD 16
__device__ __align__(64) uint32_t XTH[GUARD + (size_t)NIMG*NC2*XPLANE];
__device__ uint32_t WT2[(size_t)NCHUNK*9*16*32*4];   // [chunk][tap][mt16][lane][reg]

__device__ __forceinline__ void mma_fp16(float* d, const uint32_t* a, const uint32_t* b) {
    asm volatile(
        "mma.sync.aligned.m16n8k16.row.col.f32.f16.f16.f32 "
        "{%0,%1,%2,%3}, {%4,%5,%6,%7}, {%8,%9}, {%0,%1,%2,%3};"
        : "+f"(d[0]), "+f"(d[1]), "+f"(d[2]), "+f"(d[3])
        : "r"(a[0]), "r"(a[1]), "r"(a[2]), "r"(a[3]), "r"(b[0]), "r"(b[1]));
}
__device__ __forceinline__ void cp16(uint32_t dst, const void* src) {
    asm volatile("cp.async.cg.shared.global [%0], [%1], 16;" :: "r"(dst), "l"(src));
}
__device__ __forceinline__ void lds128(uint32_t* r, uint32_t addr) {
    asm volatile("ld.shared.v4.b32 {%0,%1,%2,%3}, [%4];"
                 : "=r"(r[0]), "=r"(r[1]), "=r"(r[2]), "=r"(r[3]) : "r"(addr));
}

// ---------------- combined transform ----------------
// blocks [0, 2048): x -> channel-pair-interleaved fp16 padded planes
// blocks [2048, 2624): K -> fp16 fragment-ordered WT2
__global__ void transform_all(const float* __restrict__ x, const float* __restrict__ k) {
    const int bid = blockIdx.x;
    const int t = threadIdx.x;
    if (bid < NIMG * NC2) {
        // plane layout: [row rr 0..57][unit u 0..59]; rr=ih+1; unit u = pixel w=u
        // (u<56), u 56..59 = zero pad; rows 0,57 = zero.
        const int n  = bid >> 6;
        const int c2 = bid & 63;
        const float* p0 = x + ((size_t)(n * CIN + 2 * c2)) * HWSZ;
        const float* p1 = p0 + HWSZ;
        uint32_t* dst = XTH + GUARD + (size_t)bid * XPLANE;
        if (bid == 0 && t < GUARD) XTH[t] = 0u;
        for (int idx = t; idx < XPLANE; idx += 256) {
            const int row = idx / 60;
            const int col = idx - row * 60;
            uint32_t v = 0u;
            if (row >= 1 && row <= 56 && col < 56) {
                const int off = (row - 1) * WW + col;
                __half2 h = __floats2half2_rn(p0[off], p1[off]);
                v = *reinterpret_cast<uint32_t*>(&h);
            }
            dst[idx] = v;
        }
    } else {
        // WT2[chunk][tap][mt][lane][j]: m = mt*16+g+(j&1)*8,
        // ch pair = chunk*16 + 2*t4 + (j>>1)*8 + {0,1}
        const int idx = (bid - NIMG * NC2) * 256 + t;   // 147456 total
        const int chunk = idx / 18432;
        int r1 = idx - chunk * 18432;
        const int tap = r1 / 2048;  r1 -= tap * 2048;
        const int mt  = r1 >> 7;
        const int ln  = (r1 >> 2) & 31;
        const int j   = r1 & 3;
        const int g   = ln >> 2, t4 = ln & 3;
        const int m   = mt * 16 + g + (j & 1) * 8;
        const int c   = chunk * 16 + 2 * t4 + (j >> 1) * 8;
        __half2 h = __floats2half2_rn(k[(size_t)(m * CIN + c) * 9 + tap],
                                      k[(size_t)(m * CIN + c + 1) * 9 + tap]);
        WT2[idx] = *reinterpret_cast<uint32_t*>(&h);
    }
}

// ---------------- main kernel ----------------
__global__ void __launch_bounds__(256, 2)
conv_mma(const float* __restrict__ bias, float* __restrict__ out) {
    extern __shared__ uint32_t sm[];
    const int t    = threadIdx.x;
    const int warp = t >> 5;
    const int lane = t & 31;
    const int g    = lane >> 2;
    const int t4   = lane & 3;
    const int wm   = warp >> 2;     // 0..1 : M halves of 32
    const int wn   = warp & 3;      // 0..3 : output row within group
    const int img  = blockIdx.y / NGROUP;
    const int grp  = blockIdx.y - img * NGROUP;
    const int oh0  = grp * ROWS_CTA;
    const int my0  = blockIdx.x * 4;
    const int m0   = blockIdx.x * TILE_M;

    uint32_t sm_u32;
    { uint64_t tmp = __cvta_generic_to_shared(sm); sm_u32 = (uint32_t)tmp; }

    float acc[2][7][4];
    #pragma unroll
    for (int mi = 0; mi < 2; ++mi)
        #pragma unroll
        for (int nj = 0; nj < 7; ++nj)
            #pragma unroll
            for (int q = 0; q < 4; ++q) acc[mi][nj][q] = 0.0f;

    const uint32_t* xg_base = XTH + GUARD + ((size_t)img * NC2) * XPLANE + (size_t)oh0 * 60;

    auto issue = [&](int chunk, int stage) {
        const uint32_t ab = sm_u32 + stage * STAGE_BYTES;
        const uint32_t bb = ab + A_UNITS * 4;
        const uint32_t* ag = WT2 + (size_t)chunk * 18432;
        // A: 1152 cp16 (4 mtiles x 9 taps x 32 lanes x 16B)
        #pragma unroll
        for (int q = 0; q < 5; ++q) {
            const int idx = q * 256 + t;
            if (idx < 1152) {
                const int tap  = idx >> 7;
                const int rem  = idx & 127;
                const int tile = rem >> 5;
                const int ln2  = rem & 31;
                cp16(ab + idx * 16,
                     ag + (size_t)tap * 2048 + (size_t)(my0 + tile) * 128 + ln2 * 4);
            }
        }
        // B: 768 cp16 = 8 c2 x 6 rows x 16 (units -4..59 of each row)
        #pragma unroll
        for (int q = 0; q < 3; ++q) {
            const int idx = q * 256 + t;
            const int c   = idx / 96;
            const int rem = idx - c * 96;
            const int row = rem >> 4;
            const int f   = rem & 15;
            cp16(bb + (c * 392 + row * 64 + f * 4) * 4,
                 xg_base + (size_t)(chunk * 8 + c) * XPLANE + row * 60 + f * 4 - 4);
        }
    };

    issue(0, 0);
    asm volatile("cp.async.commit_group;" ::: "memory");
    issue(1, 1);
    asm volatile("cp.async.commit_group;" ::: "memory");

    int stage = 0, stage2 = 2;
    for (int chunk = 0; chunk < NCHUNK; ++chunk) {
        asm volatile("cp.async.wait_group 1;" ::: "memory");
        __syncthreads();

        const uint32_t a_base = sm_u32 + stage * STAGE_BYTES + (wm * 2) * 512 + lane * 16;
        const uint32_t* Bw = sm + stage * STAGE_UNITS + A_UNITS + t4 * 392 + wn * 64 + g;

        // preload tap-0 B fragments
        uint32_t bc[7][2];
        #pragma unroll
        for (int nj = 0; nj < 7; ++nj) {
            bc[nj][0] = Bw[3 + nj * 8];
            bc[nj][1] = Bw[1568 + 3 + nj * 8];
        }

        #pragma unroll
        for (int tap = 0; tap < 9; ++tap) {
            uint32_t a[2][4];
            lds128(a[0], a_base + tap * 2048);
            lds128(a[1], a_base + tap * 2048 + 512);

            uint32_t bn[7][2];
            if (tap < 8) {
                const int tp = tap + 1;
                const int r2 = tp / 3;
                const int s2 = tp - r2 * 3;
                const int off2 = r2 * 64 + s2 + 3;
                #pragma unroll
                for (int nj = 0; nj < 7; ++nj) {
                    bn[nj][0] = Bw[off2 + nj * 8];
                    bn[nj][1] = Bw[1568 + off2 + nj * 8];
                }
            }

            #pragma unroll
            for (int mi = 0; mi < 2; ++mi)
                #pragma unroll
                for (int nj = 0; nj < 7; ++nj)
                    mma_fp16(acc[mi][nj], a[mi], bc[nj]);

            if (tap < 8) {
                #pragma unroll
                for (int nj = 0; nj < 7; ++nj) {
                    bc[nj][0] = bn[nj][0];
                    bc[nj][1] = bn[nj][1];
                }
            }
        }

        if (chunk + 2 < NCHUNK) issue(chunk + 2, stage2);
        asm volatile("cp.async.commit_group;" ::: "memory");

        stage  = (stage  == 2) ? 0 : stage  + 1;
        stage2 = (stage2 == 2) ? 0 : stage2 + 1;
    }

    // ---- epilogue ----
    const float bv = bias[0];
    const int orow = oh0 + wn;
    #pragma unroll
    for (int mi = 0; mi < 2; ++mi) {
        const int kch = m0 + wm * 32 + mi * 16 + g;
        float* o = out + ((size_t)img * KOUT + kch) * HWSZ + (size_t)orow * WW;
        #pragma unroll
        for (int nj = 0; nj < 7; ++nj) {
            const int ow = nj * 8 + 2 * t4;
            *reinterpret_cast<float2*>(o + ow) =
                make_float2(acc[mi][nj][0] + bv, acc[mi][nj][1] + bv);
            *reinterpret_cast<float2*>(o + 8 * HWSZ + ow) =
                make_float2(acc[mi][nj][2] + bv, acc[mi][nj][3] + bv);
        }
    }
}

// ---------------- host ----------------
extern "C" void kernel_launch(void* const* d_in, const int* in_sizes, int n_in,
                              void* d_out, int out_size) {
    const float* x    = (const float*)d_in[0];
    const float* K    = (const float*)d_in[1];
    const float* bias = (const float*)d_in[2];
    float* out        = (float*)d_out;

    cudaFuncSetAttribute(conv_mma, cudaFuncAttributeMaxDynamicSharedMemorySize, SMEM_BYTES);

    transform_all<<<NIMG * NC2 + 576, 256>>>(x, K);
    dim3 grid(KOUT / TILE_M, NIMG * NGROUP);   // (4, 448)
    conv_mma<<<grid, 256, SMEM_BYTES>>>(bias, out);
}

// round 10
// speedup vs baseline: 2.1108x; 1.0213x over previous
#include <cuda_runtime.h>
#include <cuda_fp16.h>
#include <cstdint>

#define CIN   128
#define KOUT  256
#define HH    56
#define WW    56
#define NIMG  32
#define HWSZ  (HH*WW)            // 3136
#define XPLANE (58*60)           // b32 units per (n,c2) plane; unit=2 fp16 ch
#define NC2   64

#define TILE_M   64
#define ROWS_CTA 4
#define NGROUP   (HH/ROWS_CTA)   // 14
#define NCHUNK   8               // chunks of 16 channels

// smem per stage (b32 units):
//  A: [tap(9)][mtile(4)][lane(32)][4] = 4608 units
//  B: [c2(8)] x (6 rows x 64 + 8 pad = 392) = 3136 units
#define A_UNITS 4608
#define B_UNITS 3136
#define STAGE_UNITS (A_UNITS + B_UNITS)      // 7744
#define STAGE_BYTES (STAGE_UNITS*4)          // 30976
#define SMEM_BYTES (2*STAGE_BYTES)           // 61952

#define GUARD 16
__device__ __align__(64) uint32_t XTH[GUARD + (size_t)NIMG*NC2*XPLANE];
__device__ uint32_t WT2[(size_t)NCHUNK*9*16*32*4];   // [chunk][tap][mt16][lane][reg]

__device__ __forceinline__ void mma_fp16(float* d, const uint32_t* a, const uint32_t* b) {
    asm volatile(
        "mma.sync.aligned.m16n8k16.row.col.f32.f16.f16.f32 "
        "{%0,%1,%2,%3}, {%4,%5,%6,%7}, {%8,%9}, {%0,%1,%2,%3};"
        : "+f"(d[0]), "+f"(d[1]), "+f"(d[2]), "+f"(d[3])
        : "r"(a[0]), "r"(a[1]), "r"(a[2]), "r"(a[3]), "r"(b[0]), "r"(b[1]));
}
__device__ __forceinline__ void cp16(uint32_t dst, const void* src) {
    asm volatile("cp.async.cg.shared.global [%0], [%1], 16;" :: "r"(dst), "l"(src));
}
__device__ __forceinline__ void lds128(uint32_t* r, uint32_t addr) {
    asm volatile("ld.shared.v4.b32 {%0,%1,%2,%3}, [%4];"
                 : "=r"(r[0]), "=r"(r[1]), "=r"(r[2]), "=r"(r[3]) : "r"(addr));
}

// ---------------- combined transform (identical to R9, passed) ----------------
__global__ void transform_all(const float* __restrict__ x, const float* __restrict__ k) {
    const int bid = blockIdx.x;
    const int t = threadIdx.x;
    if (bid < NIMG * NC2) {
        const int n  = bid >> 6;
        const int c2 = bid & 63;
        const float* p0 = x + ((size_t)(n * CIN + 2 * c2)) * HWSZ;
        const float* p1 = p0 + HWSZ;
        uint32_t* dst = XTH + GUARD + (size_t)bid * XPLANE;
        if (bid == 0 && t < GUARD) XTH[t] = 0u;
        for (int idx = t; idx < XPLANE; idx += 256) {
            const int row = idx / 60;
            const int col = idx - row * 60;
            uint32_t v = 0u;
            if (row >= 1 && row <= 56 && col < 56) {
                const int off = (row - 1) * WW + col;
                __half2 h = __floats2half2_rn(p0[off], p1[off]);
                v = *reinterpret_cast<uint32_t*>(&h);
            }
            dst[idx] = v;
        }
    } else {
        const int idx = (bid - NIMG * NC2) * 256 + t;   // 147456 total
        const int chunk = idx / 18432;
        int r1 = idx - chunk * 18432;
        const int tap = r1 / 2048;  r1 -= tap * 2048;
        const int mt  = r1 >> 7;
        const int ln  = (r1 >> 2) & 31;
        const int j   = r1 & 3;
        const int g   = ln >> 2, t4 = ln & 3;
        const int m   = mt * 16 + g + (j & 1) * 8;
        const int c   = chunk * 16 + 2 * t4 + (j >> 1) * 8;
        __half2 h = __floats2half2_rn(k[(size_t)(m * CIN + c) * 9 + tap],
                                      k[(size_t)(m * CIN + c + 1) * 9 + tap]);
        WT2[idx] = *reinterpret_cast<uint32_t*>(&h);
    }
}

// ---------------- main kernel: 4 warps, M=64 per warp, 1 row per warp ----------------
__global__ void __launch_bounds__(128, 3)
conv_mma(const float* __restrict__ bias, float* __restrict__ out) {
    extern __shared__ uint32_t sm[];
    const int t    = threadIdx.x;
    const int wn   = t >> 5;        // warp = output row within group
    const int lane = t & 31;
    const int g    = lane >> 2;
    const int t4   = lane & 3;
    const int img  = blockIdx.y / NGROUP;
    const int grp  = blockIdx.y - img * NGROUP;
    const int oh0  = grp * ROWS_CTA;
    const int my0  = blockIdx.x * 4;
    const int m0   = blockIdx.x * TILE_M;

    uint32_t sm_u32;
    { uint64_t tmp = __cvta_generic_to_shared(sm); sm_u32 = (uint32_t)tmp; }

    float acc[4][7][4];
    #pragma unroll
    for (int mi = 0; mi < 4; ++mi)
        #pragma unroll
        for (int nj = 0; nj < 7; ++nj)
            #pragma unroll
            for (int q = 0; q < 4; ++q) acc[mi][nj][q] = 0.0f;

    const uint32_t* xg_base = XTH + GUARD + ((size_t)img * NC2) * XPLANE + (size_t)oh0 * 60;

    auto issue = [&](int chunk, int stage) {
        const uint32_t ab = sm_u32 + stage * STAGE_BYTES;
        const uint32_t bb = ab + A_UNITS * 4;
        const uint32_t* ag = WT2 + (size_t)chunk * 18432;
        // A: 1152 cp16, 9 per thread
        #pragma unroll
        for (int q = 0; q < 9; ++q) {
            const int idx = q * 128 + t;
            const int tap  = idx >> 7;
            const int rem  = idx & 127;
            const int tile = rem >> 5;
            const int ln2  = rem & 31;
            cp16(ab + idx * 16,
                 ag + (size_t)tap * 2048 + (size_t)(my0 + tile) * 128 + ln2 * 4);
        }
        // B: 768 cp16 = 8 c2 x 6 rows x 16, 6 per thread
        #pragma unroll
        for (int q = 0; q < 6; ++q) {
            const int idx = q * 128 + t;
            const int c   = idx / 96;
            const int rem = idx - c * 96;
            const int row = rem >> 4;
            const int f   = rem & 15;
            cp16(bb + (c * 392 + row * 64 + f * 4) * 4,
                 xg_base + (size_t)(chunk * 8 + c) * XPLANE + row * 60 + f * 4 - 4);
        }
    };

    issue(0, 0);
    asm volatile("cp.async.commit_group;" ::: "memory");
    issue(1, 1);
    asm volatile("cp.async.commit_group;" ::: "memory");

    for (int chunk = 0; chunk < NCHUNK; ++chunk) {
        if (chunk + 2 < NCHUNK) {
            asm volatile("cp.async.wait_group 1;" ::: "memory");
        } else {
            asm volatile("cp.async.wait_group 0;" ::: "memory");
        }
        __syncthreads();

        const int stage = chunk & 1;
        const uint32_t a_base = sm_u32 + stage * STAGE_BYTES + lane * 16;
        const uint32_t* Bw = sm + stage * STAGE_UNITS + A_UNITS + t4 * 392 + wn * 64 + g;

        #pragma unroll
        for (int tap = 0; tap < 9; ++tap) {
            const int r = tap / 3;
            const int s = tap - r * 3;
            const int off = r * 64 + s + 3;

            uint32_t b[7][2];
            #pragma unroll
            for (int nj = 0; nj < 7; ++nj) {
                b[nj][0] = Bw[off + nj * 8];
                b[nj][1] = Bw[1568 + off + nj * 8];
            }
            uint32_t a[4][4];
            #pragma unroll
            for (int mi = 0; mi < 4; ++mi)
                lds128(a[mi], a_base + tap * 2048 + mi * 512);

            #pragma unroll
            for (int mi = 0; mi < 4; ++mi)
                #pragma unroll
                for (int nj = 0; nj < 7; ++nj)
                    mma_fp16(acc[mi][nj], a[mi], b[nj]);
        }
        __syncthreads();

        if (chunk + 2 < NCHUNK) {
            issue(chunk + 2, stage);
            asm volatile("cp.async.commit_group;" ::: "memory");
        }
    }

    // ---- epilogue ----
    const float bv = bias[0];
    const int orow = oh0 + wn;
    #pragma unroll
    for (int mi = 0; mi < 4; ++mi) {
        const int kch = m0 + mi * 16 + g;
        float* o = out + ((size_t)img * KOUT + kch) * HWSZ + (size_t)orow * WW;
        #pragma unroll
        for (int nj = 0; nj < 7; ++nj) {
            const int ow = nj * 8 + 2 * t4;
            *reinterpret_cast<float2*>(o + ow) =
                make_float2(acc[mi][nj][0] + bv, acc[mi][nj][1] + bv);
            *reinterpret_cast<float2*>(o + 8 * HWSZ + ow) =
                make_float2(acc[mi][nj][2] + bv, acc[mi][nj][3] + bv);
        }
    }
}

// ---------------- host ----------------
extern "C" void kernel_launch(void* const* d_in, const int* in_sizes, int n_in,
                              void* d_out, int out_size) {
    const float* x    = (const float*)d_in[0];
    const float* K    = (const float*)d_in[1];
    const float* bias = (const float*)d_in[2];
    float* out        = (float*)d_out;

    cudaFuncSetAttribute(conv_mma, cudaFuncAttributeMaxDynamicSharedMemorySize, SMEM_BYTES);

    transform_all<<<NIMG * NC2 + 576, 256>>>(x, K);
    dim3 grid(KOUT / TILE_M, NIMG * NGROUP);   // (4, 448) = 1792 CTAs of 128 thr
    conv_mma<<<grid, 128, SMEM_BYTES>>>(bias, out);
}

// round 11
// speedup vs baseline: 2.2197x; 1.0516x over previous
#include <cuda_runtime.h>
#include <cuda_fp16.h>
#include <cstdint>

#define CIN   128
#define KOUT  256
#define HH    56
#define WW    56
#define NIMG  32
#define HWSZ  (HH*WW)            // 3136
#define XPLANE (58*60)           // b32 units per (n,c2) plane; unit=2 fp16 ch
#define NC2   64

#define TILE_M   64
#define ROWS_CTA 4
#define NGROUP   (HH/ROWS_CTA)   // 14
#define NCHUNK   8               // chunks of 16 channels

// smem per stage (b32 units):
//  A: [tap(9)][mtile(4)][lane(32)][4] = 4608 units
//  B: [c2(8)] x (6 rows x 64 + 8 pad = 392) = 3136 units
#define A_UNITS 4608
#define B_UNITS 3136
#define STAGE_UNITS (A_UNITS + B_UNITS)      // 7744
#define STAGE_BYTES (STAGE_UNITS*4)          // 30976
#define SMEM_BYTES (2*STAGE_BYTES)           // 61952

#define GUARD 16
__device__ __align__(64) uint32_t XTH[GUARD + (size_t)NIMG*NC2*XPLANE];
__device__ uint32_t WT2[(size_t)NCHUNK*9*16*32*4];   // [chunk][tap][mt16][lane][reg]

__device__ __forceinline__ void mma_fp16(float* d, const uint32_t* a, const uint32_t* b) {
    asm volatile(
        "mma.sync.aligned.m16n8k16.row.col.f32.f16.f16.f32 "
        "{%0,%1,%2,%3}, {%4,%5,%6,%7}, {%8,%9}, {%0,%1,%2,%3};"
        : "+f"(d[0]), "+f"(d[1]), "+f"(d[2]), "+f"(d[3])
        : "r"(a[0]), "r"(a[1]), "r"(a[2]), "r"(a[3]), "r"(b[0]), "r"(b[1]));
}
__device__ __forceinline__ void cp16(uint32_t dst, const void* src) {
    asm volatile("cp.async.cg.shared.global [%0], [%1], 16;" :: "r"(dst), "l"(src));
}
__device__ __forceinline__ void lds128(uint32_t* r, uint32_t addr) {
    asm volatile("ld.shared.v4.b32 {%0,%1,%2,%3}, [%4];"
                 : "=r"(r[0]), "=r"(r[1]), "=r"(r[2]), "=r"(r[3]) : "r"(addr));
}
__device__ __forceinline__ uint32_t h2u(__half2 h) {
    return *reinterpret_cast<uint32_t*>(&h);
}

// ---------------- combined transform (vectorized) ----------------
// blocks [0, 2048): x -> channel-pair-interleaved fp16 padded planes (f4 in/out)
// blocks [2048, 2624): K -> fp16 fragment-ordered WT2
__global__ void transform_all(const float* __restrict__ x, const float* __restrict__ k) {
    const int bid = blockIdx.x;
    const int t = threadIdx.x;
    if (bid < NIMG * NC2) {
        const int n  = bid >> 6;
        const int c2 = bid & 63;
        const float4* p0 = reinterpret_cast<const float4*>(
            x + ((size_t)(n * CIN + 2 * c2)) * HWSZ);
        const float4* p1 = p0 + (HWSZ / 4);            // next channel plane
        uint4* dst = reinterpret_cast<uint4*>(XTH + GUARD + (size_t)bid * XPLANE);
        if (bid == 0 && t < GUARD) XTH[t] = 0u;

        const uint4 z = make_uint4(0u, 0u, 0u, 0u);
        // halo zeros: row 0 (15 uint4), row 57 (15), right pad of rows 1..56 (56)
        if (t < 15) dst[t] = z;
        else if (t < 30) dst[855 + (t - 15)] = z;               // 57*60/4 = 855
        else if (t < 86) {
            const int row = t - 30 + 1;                          // 1..56
            dst[(row * 60 + 56) >> 2] = z;
        }
        // data: 784 uint4 (56 rows x 14)
        #pragma unroll
        for (int q = 0; q < 4; ++q) {
            const int idx = q * 256 + t;
            if (idx < 784) {
                const int row = idx / 14;
                const int f   = idx - row * 14;
                const float4 a = p0[idx];
                const float4 b = p1[idx];
                uint4 v;
                v.x = h2u(__floats2half2_rn(a.x, b.x));
                v.y = h2u(__floats2half2_rn(a.y, b.y));
                v.z = h2u(__floats2half2_rn(a.z, b.z));
                v.w = h2u(__floats2half2_rn(a.w, b.w));
                dst[(row + 1) * 15 + f] = v;
            }
        }
    } else {
        const int idx = (bid - NIMG * NC2) * 256 + t;   // 147456 total
        const int chunk = idx / 18432;
        int r1 = idx - chunk * 18432;
        const int tap = r1 / 2048;  r1 -= tap * 2048;
        const int mt  = r1 >> 7;
        const int ln  = (r1 >> 2) & 31;
        const int j   = r1 & 3;
        const int g   = ln >> 2, t4 = ln & 3;
        const int m   = mt * 16 + g + (j & 1) * 8;
        const int c   = chunk * 16 + 2 * t4 + (j >> 1) * 8;
        __half2 h = __floats2half2_rn(k[(size_t)(m * CIN + c) * 9 + tap],
                                      k[(size_t)(m * CIN + c + 1) * 9 + tap]);
        WT2[idx] = h2u(h);
    }
}

// ---------------- main kernel: 4 warps, M=64 per warp, 1 row per warp ----------------
__global__ void __launch_bounds__(128, 3)
conv_mma(const float* __restrict__ bias, float* __restrict__ out) {
    extern __shared__ uint32_t sm[];
    const int t    = threadIdx.x;
    const int wn   = t >> 5;        // warp = output row within group
    const int lane = t & 31;
    const int g    = lane >> 2;
    const int t4   = lane & 3;
    const int img  = blockIdx.y / NGROUP;
    const int grp  = blockIdx.y - img * NGROUP;
    const int oh0  = grp * ROWS_CTA;
    const int my0  = blockIdx.x * 4;
    const int m0   = blockIdx.x * TILE_M;

    uint32_t sm_u32;
    { uint64_t tmp = __cvta_generic_to_shared(sm); sm_u32 = (uint32_t)tmp; }

    float acc[4][7][4];
    #pragma unroll
    for (int mi = 0; mi < 4; ++mi)
        #pragma unroll
        for (int nj = 0; nj < 7; ++nj)
            #pragma unroll
            for (int q = 0; q < 4; ++q) acc[mi][nj][q] = 0.0f;

    const uint32_t* xg_base = XTH + GUARD + ((size_t)img * NC2) * XPLANE + (size_t)oh0 * 60;

    auto issue = [&](int chunk, int stage) {
        const uint32_t ab = sm_u32 + stage * STAGE_BYTES;
        const uint32_t bb = ab + A_UNITS * 4;
        const uint32_t* ag = WT2 + (size_t)chunk * 18432;
        // A: 1152 cp16, 9 per thread
        #pragma unroll
        for (int q = 0; q < 9; ++q) {
            const int idx = q * 128 + t;
            const int tap  = idx >> 7;
            const int rem  = idx & 127;
            const int tile = rem >> 5;
            const int ln2  = rem & 31;
            cp16(ab + idx * 16,
                 ag + (size_t)tap * 2048 + (size_t)(my0 + tile) * 128 + ln2 * 4);
        }
        // B: 768 cp16 = 8 c2 x 6 rows x 16, 6 per thread
        #pragma unroll
        for (int q = 0; q < 6; ++q) {
            const int idx = q * 128 + t;
            const int c   = idx / 96;
            const int rem = idx - c * 96;
            const int row = rem >> 4;
            const int f   = rem & 15;
            cp16(bb + (c * 392 + row * 64 + f * 4) * 4,
                 xg_base + (size_t)(chunk * 8 + c) * XPLANE + row * 60 + f * 4 - 4);
        }
    };

    issue(0, 0);
    asm volatile("cp.async.commit_group;" ::: "memory");
    issue(1, 1);
    asm volatile("cp.async.commit_group;" ::: "memory");

    for (int chunk = 0; chunk < NCHUNK; ++chunk) {
        if (chunk + 2 < NCHUNK) {
            asm volatile("cp.async.wait_group 1;" ::: "memory");
        } else {
            asm volatile("cp.async.wait_group 0;" ::: "memory");
        }
        __syncthreads();

        const int stage = chunk & 1;
        const uint32_t a_base = sm_u32 + stage * STAGE_BYTES + lane * 16;
        const uint32_t* Bw = sm + stage * STAGE_UNITS + A_UNITS + t4 * 392 + wn * 64 + g;

        #pragma unroll
        for (int tap = 0; tap < 9; ++tap) {
            const int r = tap / 3;
            const int s = tap - r * 3;
            const int off = r * 64 + s + 3;

            uint32_t b[7][2];
            #pragma unroll
            for (int nj = 0; nj < 7; ++nj) {
                b[nj][0] = Bw[off + nj * 8];
                b[nj][1] = Bw[1568 + off + nj * 8];
            }
            uint32_t a[4][4];
            #pragma unroll
            for (int mi = 0; mi < 4; ++mi)
                lds128(a[mi], a_base + tap * 2048 + mi * 512);

            #pragma unroll
            for (int mi = 0; mi < 4; ++mi)
                #pragma unroll
                for (int nj = 0; nj < 7; ++nj)
                    mma_fp16(acc[mi][nj], a[mi], b[nj]);
        }
        __syncthreads();

        if (chunk + 2 < NCHUNK) {
            issue(chunk + 2, stage);
            asm volatile("cp.async.commit_group;" ::: "memory");
        }
    }

    // ---- epilogue ----
    const float bv = bias[0];
    const int orow = oh0 + wn;
    #pragma unroll
    for (int mi = 0; mi < 4; ++mi) {
        const int kch = m0 + mi * 16 + g;
        float* o = out + ((size_t)img * KOUT + kch) * HWSZ + (size_t)orow * WW;
        #pragma unroll
        for (int nj = 0; nj < 7; ++nj) {
            const int ow = nj * 8 + 2 * t4;
            *reinterpret_cast<float2*>(o + ow) =
                make_float2(acc[mi][nj][0] + bv, acc[mi][nj][1] + bv);
            *reinterpret_cast<float2*>(o + 8 * HWSZ + ow) =
                make_float2(acc[mi][nj][2] + bv, acc[mi][nj][3] + bv);
        }
    }
}

// ---------------- host ----------------
extern "C" void kernel_launch(void* const* d_in, const int* in_sizes, int n_in,
                              void* d_out, int out_size) {
    const float* x    = (const float*)d_in[0];
    const float* K    = (const float*)d_in[1];
    const float* bias = (const float*)d_in[2];
    float* out        = (float*)d_out;

    cudaFuncSetAttribute(conv_mma, cudaFuncAttributeMaxDynamicSharedMemorySize, SMEM_BYTES);

    transform_all<<<NIMG * NC2 + 576, 256>>>(x, K);
    dim3 grid(KOUT / TILE_M, NIMG * NGROUP);   // (4, 448) = 1792 CTAs of 128 thr
    conv_mma<<<grid, 128, SMEM_BYTES>>>(bias, out);
}

// round 12
// speedup vs baseline: 2.2363x; 1.0075x over previous
#include <cuda_runtime.h>
#include <cuda_fp16.h>
#include <cstdint>

#define CIN   128
#define KOUT  256
#define HH    56
#define WW    56
#define NIMG  32
#define HWSZ  (HH*WW)            // 3136
#define XPLANE (58*60)           // b32 units per (n,c2) plane; unit=2 fp16 ch
#define NC2   64

#define TILE_M   64
#define ROWS_CTA 4
#define NGROUP   (HH/ROWS_CTA)   // 14
#define NCHUNK   8               // chunks of 16 channels

// smem per stage (b32 units):
//  A: [tap(9)][mtile(4)][lane(32)][4] = 4608 units
//  B: [c2(8)] x (6 rows x 64 + 8 pad = 392) = 3136 units
#define A_UNITS 4608
#define B_UNITS 3136
#define STAGE_UNITS (A_UNITS + B_UNITS)      // 7744
#define STAGE_BYTES (STAGE_UNITS*4)          // 30976
#define STAGES 3
#define SMEM_BYTES (STAGES*STAGE_BYTES)      // 92928

#define GUARD 16
__device__ __align__(64) uint32_t XTH[GUARD + (size_t)NIMG*NC2*XPLANE];
__device__ uint32_t WT2[(size_t)NCHUNK*9*16*32*4];   // [chunk][tap][mt16][lane][reg]

__device__ __forceinline__ void mma_fp16(float* d, const uint32_t* a, const uint32_t* b) {
    asm volatile(
        "mma.sync.aligned.m16n8k16.row.col.f32.f16.f16.f32 "
        "{%0,%1,%2,%3}, {%4,%5,%6,%7}, {%8,%9}, {%0,%1,%2,%3};"
        : "+f"(d[0]), "+f"(d[1]), "+f"(d[2]), "+f"(d[3])
        : "r"(a[0]), "r"(a[1]), "r"(a[2]), "r"(a[3]), "r"(b[0]), "r"(b[1]));
}
__device__ __forceinline__ void cp16(uint32_t dst, const void* src) {
    asm volatile("cp.async.cg.shared.global [%0], [%1], 16;" :: "r"(dst), "l"(src));
}
__device__ __forceinline__ void lds128(uint32_t* r, uint32_t addr) {
    asm volatile("ld.shared.v4.b32 {%0,%1,%2,%3}, [%4];"
                 : "=r"(r[0]), "=r"(r[1]), "=r"(r[2]), "=r"(r[3]) : "r"(addr));
}
__device__ __forceinline__ uint32_t h2u(__half2 h) {
    return *reinterpret_cast<uint32_t*>(&h);
}

// ---------------- combined transform (vectorized, identical to R11) ----------------
__global__ void transform_all(const float* __restrict__ x, const float* __restrict__ k) {
    const int bid = blockIdx.x;
    const int t = threadIdx.x;
    if (bid < NIMG * NC2) {
        const int n  = bid >> 6;
        const int c2 = bid & 63;
        const float4* p0 = reinterpret_cast<const float4*>(
            x + ((size_t)(n * CIN + 2 * c2)) * HWSZ);
        const float4* p1 = p0 + (HWSZ / 4);
        uint4* dst = reinterpret_cast<uint4*>(XTH + GUARD + (size_t)bid * XPLANE);
        if (bid == 0 && t < GUARD) XTH[t] = 0u;

        const uint4 z = make_uint4(0u, 0u, 0u, 0u);
        if (t < 15) dst[t] = z;
        else if (t < 30) dst[855 + (t - 15)] = z;
        else if (t < 86) {
            const int row = t - 30 + 1;
            dst[(row * 60 + 56) >> 2] = z;
        }
        #pragma unroll
        for (int q = 0; q < 4; ++q) {
            const int idx = q * 256 + t;
            if (idx < 784) {
                const int row = idx / 14;
                const int f   = idx - row * 14;
                const float4 a = p0[idx];
                const float4 b = p1[idx];
                uint4 v;
                v.x = h2u(__floats2half2_rn(a.x, b.x));
                v.y = h2u(__floats2half2_rn(a.y, b.y));
                v.z = h2u(__floats2half2_rn(a.z, b.z));
                v.w = h2u(__floats2half2_rn(a.w, b.w));
                dst[(row + 1) * 15 + f] = v;
            }
        }
    } else {
        const int idx = (bid - NIMG * NC2) * 256 + t;   // 147456 total
        const int chunk = idx / 18432;
        int r1 = idx - chunk * 18432;
        const int tap = r1 / 2048;  r1 -= tap * 2048;
        const int mt  = r1 >> 7;
        const int ln  = (r1 >> 2) & 31;
        const int j   = r1 & 3;
        const int g   = ln >> 2, t4 = ln & 3;
        const int m   = mt * 16 + g + (j & 1) * 8;
        const int c   = chunk * 16 + 2 * t4 + (j >> 1) * 8;
        __half2 h = __floats2half2_rn(k[(size_t)(m * CIN + c) * 9 + tap],
                                      k[(size_t)(m * CIN + c + 1) * 9 + tap]);
        WT2[idx] = h2u(h);
    }
}

// ---------------- main kernel: 4 warps, M=64/warp, 3-stage single-sync ----------------
__global__ void __launch_bounds__(128, 2)
conv_mma(const float* __restrict__ bias, float* __restrict__ out) {
    extern __shared__ uint32_t sm[];
    const int t    = threadIdx.x;
    const int wn   = t >> 5;        // warp = output row within group
    const int lane = t & 31;
    const int g    = lane >> 2;
    const int t4   = lane & 3;
    const int img  = blockIdx.y / NGROUP;
    const int grp  = blockIdx.y - img * NGROUP;
    const int oh0  = grp * ROWS_CTA;
    const int my0  = blockIdx.x * 4;
    const int m0   = blockIdx.x * TILE_M;

    uint32_t sm_u32;
    { uint64_t tmp = __cvta_generic_to_shared(sm); sm_u32 = (uint32_t)tmp; }

    float acc[4][7][4];
    #pragma unroll
    for (int mi = 0; mi < 4; ++mi)
        #pragma unroll
        for (int nj = 0; nj < 7; ++nj)
            #pragma unroll
            for (int q = 0; q < 4; ++q) acc[mi][nj][q] = 0.0f;

    const uint32_t* xg_base = XTH + GUARD + ((size_t)img * NC2) * XPLANE + (size_t)oh0 * 60;

    auto issue = [&](int chunk, int stage) {
        const uint32_t ab = sm_u32 + stage * STAGE_BYTES;
        const uint32_t bb = ab + A_UNITS * 4;
        const uint32_t* ag = WT2 + (size_t)chunk * 18432;
        #pragma unroll
        for (int q = 0; q < 9; ++q) {
            const int idx = q * 128 + t;
            const int tap  = idx >> 7;
            const int rem  = idx & 127;
            const int tile = rem >> 5;
            const int ln2  = rem & 31;
            cp16(ab + idx * 16,
                 ag + (size_t)tap * 2048 + (size_t)(my0 + tile) * 128 + ln2 * 4);
        }
        #pragma unroll
        for (int q = 0; q < 6; ++q) {
            const int idx = q * 128 + t;
            const int c   = idx / 96;
            const int rem = idx - c * 96;
            const int row = rem >> 4;
            const int f   = rem & 15;
            cp16(bb + (c * 392 + row * 64 + f * 4) * 4,
                 xg_base + (size_t)(chunk * 8 + c) * XPLANE + row * 60 + f * 4 - 4);
        }
    };

    issue(0, 0);
    asm volatile("cp.async.commit_group;" ::: "memory");
    issue(1, 1);
    asm volatile("cp.async.commit_group;" ::: "memory");

    int stage = 0, stage2 = 2;
    for (int chunk = 0; chunk < NCHUNK; ++chunk) {
        if (chunk + 1 < NCHUNK) {
            asm volatile("cp.async.wait_group 1;" ::: "memory");
        } else {
            asm volatile("cp.async.wait_group 0;" ::: "memory");
        }
        // single sync: proves all warps finished reading stage (chunk-1)%3 ==
        // stage2, so the end-of-chunk issue into stage2 is race-free.
        __syncthreads();

        const uint32_t a_base = sm_u32 + stage * STAGE_BYTES + lane * 16;
        const uint32_t* Bw = sm + stage * STAGE_UNITS + A_UNITS + t4 * 392 + wn * 64 + g;

        #pragma unroll
        for (int tap = 0; tap < 9; ++tap) {
            const int r = tap / 3;
            const int s = tap - r * 3;
            const int off = r * 64 + s + 3;

            uint32_t b[7][2];
            #pragma unroll
            for (int nj = 0; nj < 7; ++nj) {
                b[nj][0] = Bw[off + nj * 8];
                b[nj][1] = Bw[1568 + off + nj * 8];
            }
            uint32_t a[4][4];
            #pragma unroll
            for (int mi = 0; mi < 4; ++mi)
                lds128(a[mi], a_base + tap * 2048 + mi * 512);

            #pragma unroll
            for (int mi = 0; mi < 4; ++mi)
                #pragma unroll
                for (int nj = 0; nj < 7; ++nj)
                    mma_fp16(acc[mi][nj], a[mi], b[nj]);
        }

        if (chunk + 2 < NCHUNK) {
            issue(chunk + 2, stage2);
            asm volatile("cp.async.commit_group;" ::: "memory");
        }

        stage  = (stage  == 2) ? 0 : stage  + 1;
        stage2 = (stage2 == 2) ? 0 : stage2 + 1;
    }

    // ---- epilogue ----
    const float bv = bias[0];
    const int orow = oh0 + wn;
    #pragma unroll
    for (int mi = 0; mi < 4; ++mi) {
        const int kch = m0 + mi * 16 + g;
        float* o = out + ((size_t)img * KOUT + kch) * HWSZ + (size_t)orow * WW;
        #pragma unroll
        for (int nj = 0; nj < 7; ++nj) {
            const int ow = nj * 8 + 2 * t4;
            *reinterpret_cast<float2*>(o + ow) =
                make_float2(acc[mi][nj][0] + bv, acc[mi][nj][1] + bv);
            *reinterpret_cast<float2*>(o + 8 * HWSZ + ow) =
                make_float2(acc[mi][nj][2] + bv, acc[mi][nj][3] + bv);
        }
    }
}

// ---------------- host ----------------
extern "C" void kernel_launch(void* const* d_in, const int* in_sizes, int n_in,
                              void* d_out, int out_size) {
    const float* x    = (const float*)d_in[0];
    const float* K    = (const float*)d_in[1];
    const float* bias = (const float*)d_in[2];
    float* out        = (float*)d_out;

    cudaFuncSetAttribute(conv_mma, cudaFuncAttributeMaxDynamicSharedMemorySize, SMEM_BYTES);

    transform_all<<<NIMG * NC2 + 576, 256>>>(x, K);
    dim3 grid(KOUT / TILE_M, NIMG * NGROUP);   // (4, 448) = 1792 CTAs of 128 thr
    conv_mma<<<grid, 128, SMEM_BYTES>>>(bias, out);
}

// round 13
// speedup vs baseline: 2.2396x; 1.0015x over previous
#include <cuda_runtime.h>
#include <cuda_fp16.h>
#include <cstdint>

#define CIN   128
#define KOUT  256
#define HH    56
#define WW    56
#define NIMG  32
#define HWSZ  (HH*WW)            // 3136
#define XPLANE (58*60)           // b32 units per (n,c2) plane; unit=2 fp16 ch
#define NC2   64

#define TILE_M   64
#define ROWS_CTA 4
#define NGROUP   (HH/ROWS_CTA)   // 14
#define NCHUNK   8               // chunks of 16 channels

// smem per stage (b32 units):
//  A: [tap(9)][mtile(4)][lane(32)][4] = 4608 units
//  B: [c2(8)] x (6 rows x 64 + 8 pad = 392) = 3136 units
#define A_UNITS 4608
#define B_UNITS 3136
#define STAGE_UNITS (A_UNITS + B_UNITS)      // 7744
#define STAGE_BYTES (STAGE_UNITS*4)          // 30976
#define SMEM_BYTES (2*STAGE_BYTES)           // 61952

#define GUARD 16
__device__ __align__(64) uint32_t XTH[GUARD + (size_t)NIMG*NC2*XPLANE];
__device__ uint32_t WT2[(size_t)NCHUNK*9*16*32*4];   // [chunk][tap][mt16][lane][reg]

__device__ __forceinline__ void mma_fp16(float* d, const uint32_t* a, const uint32_t* b) {
    asm volatile(
        "mma.sync.aligned.m16n8k16.row.col.f32.f16.f16.f32 "
        "{%0,%1,%2,%3}, {%4,%5,%6,%7}, {%8,%9}, {%0,%1,%2,%3};"
        : "+f"(d[0]), "+f"(d[1]), "+f"(d[2]), "+f"(d[3])
        : "r"(a[0]), "r"(a[1]), "r"(a[2]), "r"(a[3]), "r"(b[0]), "r"(b[1]));
}
__device__ __forceinline__ void cp16(uint32_t dst, const void* src) {
    asm volatile("cp.async.cg.shared.global [%0], [%1], 16;" :: "r"(dst), "l"(src));
}
__device__ __forceinline__ void lds128(uint32_t* r, uint32_t addr) {
    asm volatile("ld.shared.v4.b32 {%0,%1,%2,%3}, [%4];"
                 : "=r"(r[0]), "=r"(r[1]), "=r"(r[2]), "=r"(r[3]) : "r"(addr));
}
__device__ __forceinline__ uint32_t h2u(__half2 h) {
    return *reinterpret_cast<uint32_t*>(&h);
}

// ---------------- combined transform (vectorized; identical to R11/R12) ----------------
__global__ void transform_all(const float* __restrict__ x, const float* __restrict__ k) {
    const int bid = blockIdx.x;
    const int t = threadIdx.x;
    if (bid < NIMG * NC2) {
        const int n  = bid >> 6;
        const int c2 = bid & 63;
        const float4* p0 = reinterpret_cast<const float4*>(
            x + ((size_t)(n * CIN + 2 * c2)) * HWSZ);
        const float4* p1 = p0 + (HWSZ / 4);
        uint4* dst = reinterpret_cast<uint4*>(XTH + GUARD + (size_t)bid * XPLANE);
        if (bid == 0 && t < GUARD) XTH[t] = 0u;

        const uint4 z = make_uint4(0u, 0u, 0u, 0u);
        if (t < 15) dst[t] = z;
        else if (t < 30) dst[855 + (t - 15)] = z;
        else if (t < 86) {
            const int row = t - 30 + 1;
            dst[(row * 60 + 56) >> 2] = z;
        }
        #pragma unroll
        for (int q = 0; q < 4; ++q) {
            const int idx = q * 256 + t;
            if (idx < 784) {
                const int row = idx / 14;
                const int f   = idx - row * 14;
                const float4 a = p0[idx];
                const float4 b = p1[idx];
                uint4 v;
                v.x = h2u(__floats2half2_rn(a.x, b.x));
                v.y = h2u(__floats2half2_rn(a.y, b.y));
                v.z = h2u(__floats2half2_rn(a.z, b.z));
                v.w = h2u(__floats2half2_rn(a.w, b.w));
                dst[(row + 1) * 15 + f] = v;
            }
        }
    } else {
        const int idx = (bid - NIMG * NC2) * 256 + t;   // 147456 total
        const int chunk = idx / 18432;
        int r1 = idx - chunk * 18432;
        const int tap = r1 / 2048;  r1 -= tap * 2048;
        const int mt  = r1 >> 7;
        const int ln  = (r1 >> 2) & 31;
        const int j   = r1 & 3;
        const int g   = ln >> 2, t4 = ln & 3;
        const int m   = mt * 16 + g + (j & 1) * 8;
        const int c   = chunk * 16 + 2 * t4 + (j >> 1) * 8;
        __half2 h = __floats2half2_rn(k[(size_t)(m * CIN + c) * 9 + tap],
                                      k[(size_t)(m * CIN + c + 1) * 9 + tap]);
        WT2[idx] = h2u(h);
    }
}

// ---------------- main kernel: 4 warps, M=64/warp, 2-stage, 3 CTAs/SM ----------------
__global__ void __launch_bounds__(128, 3)
conv_mma(const float* __restrict__ bias, float* __restrict__ out) {
    extern __shared__ uint32_t sm[];
    const int t    = threadIdx.x;
    const int wn   = t >> 5;        // warp = output row within group
    const int lane = t & 31;
    const int g    = lane >> 2;
    const int t4   = lane & 3;
    const int img  = blockIdx.y / NGROUP;
    const int grp  = blockIdx.y - img * NGROUP;
    const int oh0  = grp * ROWS_CTA;
    const int my0  = blockIdx.x * 4;
    const int m0   = blockIdx.x * TILE_M;

    uint32_t sm_u32;
    { uint64_t tmp = __cvta_generic_to_shared(sm); sm_u32 = (uint32_t)tmp; }

    float acc[4][7][4];
    #pragma unroll
    for (int mi = 0; mi < 4; ++mi)
        #pragma unroll
        for (int nj = 0; nj < 7; ++nj)
            #pragma unroll
            for (int q = 0; q < 4; ++q) acc[mi][nj][q] = 0.0f;

    const uint32_t* xg_base = XTH + GUARD + ((size_t)img * NC2) * XPLANE + (size_t)oh0 * 60;

    auto issue = [&](int chunk, int stage) {
        const uint32_t ab = sm_u32 + stage * STAGE_BYTES;
        const uint32_t bb = ab + A_UNITS * 4;
        const uint32_t* ag = WT2 + (size_t)chunk * 18432;
        // A: 1152 cp16, 9 per thread
        #pragma unroll
        for (int q = 0; q < 9; ++q) {
            const int idx = q * 128 + t;
            const int tap  = idx >> 7;
            const int rem  = idx & 127;
            const int tile = rem >> 5;
            const int ln2  = rem & 31;
            cp16(ab + idx * 16,
                 ag + (size_t)tap * 2048 + (size_t)(my0 + tile) * 128 + ln2 * 4);
        }
        // B: 768 cp16 = 8 c2 x 6 rows x 16, 6 per thread
        #pragma unroll
        for (int q = 0; q < 6; ++q) {
            const int idx = q * 128 + t;
            const int c   = idx / 96;
            const int rem = idx - c * 96;
            const int row = rem >> 4;
            const int f   = rem & 15;
            cp16(bb + (c * 392 + row * 64 + f * 4) * 4,
                 xg_base + (size_t)(chunk * 8 + c) * XPLANE + row * 60 + f * 4 - 4);
        }
    };

    issue(0, 0);
    asm volatile("cp.async.commit_group;" ::: "memory");
    issue(1, 1);
    asm volatile("cp.async.commit_group;" ::: "memory");

    for (int chunk = 0; chunk < NCHUNK; ++chunk) {
        if (chunk + 1 < NCHUNK) {
            asm volatile("cp.async.wait_group 1;" ::: "memory");
        } else {
            asm volatile("cp.async.wait_group 0;" ::: "memory");
        }
        __syncthreads();

        const int stage = chunk & 1;
        const uint32_t a_base = sm_u32 + stage * STAGE_BYTES + lane * 16;
        const uint32_t* Bw = sm + stage * STAGE_UNITS + A_UNITS + t4 * 392 + wn * 64 + g;

        #pragma unroll
        for (int tap = 0; tap < 9; ++tap) {
            const int r = tap / 3;
            const int s = tap - r * 3;
            const int off = r * 64 + s + 3;

            uint32_t b[7][2];
            #pragma unroll
            for (int nj = 0; nj < 7; ++nj) {
                b[nj][0] = Bw[off + nj * 8];
                b[nj][1] = Bw[1568 + off + nj * 8];
            }
            uint32_t a[4][4];
            #pragma unroll
            for (int mi = 0; mi < 4; ++mi)
                lds128(a[mi], a_base + tap * 2048 + mi * 512);

            #pragma unroll
            for (int mi = 0; mi < 4; ++mi)
                #pragma unroll
                for (int nj = 0; nj < 7; ++nj)
                    mma_fp16(acc[mi][nj], a[mi], b[nj]);
        }
        __syncthreads();

        if (chunk + 2 < NCHUNK) {
            issue(chunk + 2, stage);
            asm volatile("cp.async.commit_group;" ::: "memory");
        }
    }

    // ---- epilogue ----
    const float bv = bias[0];
    const int orow = oh0 + wn;
    #pragma unroll
    for (int mi = 0; mi < 4; ++mi) {
        const int kch = m0 + mi * 16 + g;
        float* o = out + ((size_t)img * KOUT + kch) * HWSZ + (size_t)orow * WW;
        #pragma unroll
        for (int nj = 0; nj < 7; ++nj) {
            const int ow = nj * 8 + 2 * t4;
            *reinterpret_cast<float2*>(o + ow) =
                make_float2(acc[mi][nj][0] + bv, acc[mi][nj][1] + bv);
            *reinterpret_cast<float2*>(o + 8 * HWSZ + ow) =
                make_float2(acc[mi][nj][2] + bv, acc[mi][nj][3] + bv);
        }
    }
}

// ---------------- host ----------------
extern "C" void kernel_launch(void* const* d_in, const int* in_sizes, int n_in,
                              void* d_out, int out_size) {
    const float* x    = (const float*)d_in[0];
    const float* K    = (const float*)d_in[1];
    const float* bias = (const float*)d_in[2];
    float* out        = (float*)d_out;

    cudaFuncSetAttribute(conv_mma, cudaFuncAttributeMaxDynamicSharedMemorySize, SMEM_BYTES);

    transform_all<<<NIMG * NC2 + 576, 256>>>(x, K);
    dim3 grid(KOUT / TILE_M, NIMG * NGROUP);   // (4, 448) = 1792 CTAs of 128 thr
    conv_mma<<<grid, 128, SMEM_BYTES>>>(bias, out);
}